// round 1
// baseline (speedup 1.0000x reference)
#include <cuda_runtime.h>

// CPHASE on qubits (0,1) of a 22-qubit batched state (B=4).
// state shape: (2,)*22 + (4,) -> flattened 2^22 * 4 = 2^24 floats each for re/im.
// Qubits (0,1) are the slowest axes => |11> subspace is the LAST quarter of the
// flattened array. Batch is the innermost axis => one float4 = 4 batch lanes.
//
// out[0:2^24]       = new re
// out[2^24:2^25]    = new im

#define N_FLOATS (1u << 24)          // 2^22 amplitudes * 4 batch
#define N4       (1u << 22)          // float4 count per plane
#define THRESH   (3u << 20)          // first 3/4 of float4s: identity

__global__ __launch_bounds__(256) void cphase_kernel(
    const float4* __restrict__ re,
    const float4* __restrict__ im,
    const float*  __restrict__ theta,
    float4* __restrict__ out)
{
    unsigned i = blockIdx.x * blockDim.x + threadIdx.x;   // 0 .. N4-1
    float4 r = re[i];
    float4 m = im[i];

    float4 orr, omm;
    if (i >= THRESH) {
        // |11> block: rotate each batch lane by theta[b]
        float c0, s0, c1, s1, c2, s2, c3, s3;
        __sincosf(theta[0], &s0, &c0);
        __sincosf(theta[1], &s1, &c1);
        __sincosf(theta[2], &s2, &c2);
        __sincosf(theta[3], &s3, &c3);
        orr.x = fmaf(r.x, c0, -m.x * s0);  omm.x = fmaf(r.x, s0, m.x * c0);
        orr.y = fmaf(r.y, c1, -m.y * s1);  omm.y = fmaf(r.y, s1, m.y * c1);
        orr.z = fmaf(r.z, c2, -m.z * s2);  omm.z = fmaf(r.z, s2, m.z * c2);
        orr.w = fmaf(r.w, c3, -m.w * s3);  omm.w = fmaf(r.w, s3, m.w * c3);
    } else {
        orr = r;
        omm = m;
    }

    out[i]      = orr;       // re plane
    out[i + N4] = omm;       // im plane
}

extern "C" void kernel_launch(void* const* d_in, const int* in_sizes, int n_in,
                              void* d_out, int out_size)
{
    const float4* re    = (const float4*)d_in[0];
    const float4* im    = (const float4*)d_in[1];
    const float*  theta = (const float*)d_in[2];
    float4* out = (float4*)d_out;

    dim3 block(256);
    dim3 grid(N4 / 256);   // 16384 blocks, exact cover
    cphase_kernel<<<grid, block>>>(re, im, theta, out);
}